// round 2
// baseline (speedup 1.0000x reference)
#include <cuda_runtime.h>
#include <math.h>

// Problem constants
#define B_   64
#define S_   1000
#define D_   512      // dec hidden
#define K2_  1024     // 2*ENC
#define KTOT 1536     // D_ + K2_
#define M_   (B_ * S_)   // 64000 GEMM rows

// Scratch (no cudaMalloc allowed)
__device__ float g_hW[B_ * D_];        // hidden @ W_top + bias, per batch
__device__ float g_logits[M_];         // pre-softmax attention logits

// ---------------------------------------------------------------------------
// Kernel 1: g_hW[b][n] = attn_b[n] + sum_k hidden[b][k] * attn_w[k][n]
// grid(64), block(512)
// ---------------------------------------------------------------------------
__global__ void hw_kernel(const float* __restrict__ hidden,
                          const float* __restrict__ attn_w,
                          const float* __restrict__ attn_b) {
    __shared__ float sh[D_];
    const int b = blockIdx.x;
    const int n = threadIdx.x;
    sh[n] = hidden[b * D_ + n];
    __syncthreads();
    float acc = attn_b[n];
    #pragma unroll 8
    for (int k = 0; k < D_; k++) {
        acc += sh[k] * attn_w[k * D_ + n];   // coalesced over n
    }
    g_hW[b * D_ + n] = acc;
}

// ---------------------------------------------------------------------------
// Kernel 2: main fused GEMM + tanh + v-dot.
// logits[m] = sum_n v[n] * tanh( enc[m,:] @ W_bot[:,n] + g_hW[b(m), n] )
// Tile: TM=64 rows per CTA, loop n in TN=64 chunks (full N=512), TK=16.
// 256 threads, each computes a 4x4 microtile; per-row v-weighted tanh sum
// accumulated in registers, reduced across tx lanes via shuffles.
// grid(1000), block(256)
// ---------------------------------------------------------------------------
#define TM 64
#define TN 64
#define TK 16

__global__ __launch_bounds__(256)
void attn_gemm_kernel(const float* __restrict__ enc,     // [M_, K2_]
                      const float* __restrict__ attn_w,  // [KTOT, D_]
                      const float* __restrict__ v) {
    // NOTE: no +1 pad on As — row stride must stay 16 floats (64B) so the
    // float4 STS below is 16B-aligned. Reads of As[row][kk] hit only 2
    // distinct addresses per warp (2 ty values) -> broadcast, conflict-free.
    __shared__ float As[TM][TK];
    __shared__ float Bs[TK][TN];
    __shared__ float sv[D_];

    const int t  = threadIdx.x;        // 0..255
    const int tx = t & 15;             // col group
    const int ty = t >> 4;             // row group
    const int m0 = blockIdx.x * TM;

    // cache v once
    sv[t]       = v[t];
    sv[t + 256] = v[t + 256];

    // per-row batch index + hW row pointer (rows may straddle a batch boundary)
    const float* hWp[4];
    #pragma unroll
    for (int r = 0; r < 4; r++) {
        int m = m0 + ty * 4 + r;
        hWp[r] = g_hW + (m / S_) * D_;
    }

    // A-load mapping: thread t loads float4 at row t>>2, col (t&3)*4
    const int ar  = t >> 2;
    const int ac4 = (t & 3) * 4;
    // B-load mapping: thread t loads float4 at row t>>4, col (t&15)*4
    const int br  = t >> 4;
    const int bc4 = (t & 15) * 4;

    const float* Abase = enc + (size_t)(m0 + ar) * K2_ + ac4;
    // W_bot row k lives at attn_w[(D_ + k) * D_]
    const float* Bbase = attn_w + (size_t)(D_ + br) * D_ + bc4;

    float rowsum[4] = {0.f, 0.f, 0.f, 0.f};

    for (int n0 = 0; n0 < D_; n0 += TN) {
        float acc[4][4];
        #pragma unroll
        for (int r = 0; r < 4; r++)
            #pragma unroll
            for (int c = 0; c < 4; c++) acc[r][c] = 0.f;

        for (int k0 = 0; k0 < K2_; k0 += TK) {
            // issue global loads before the barrier (prefetch into regs)
            float4 av = *reinterpret_cast<const float4*>(Abase + k0);
            float4 bv = *reinterpret_cast<const float4*>(Bbase + (size_t)k0 * D_ + n0);
            __syncthreads();   // protect previous iteration's smem reads
            *reinterpret_cast<float4*>(&As[ar][ac4]) = av;
            *reinterpret_cast<float4*>(&Bs[br][bc4]) = bv;
            __syncthreads();

            #pragma unroll
            for (int kk = 0; kk < TK; kk++) {
                float4 b4 = *reinterpret_cast<const float4*>(&Bs[kk][tx * 4]);
                #pragma unroll
                for (int r = 0; r < 4; r++) {
                    float a = As[ty * 4 + r][kk];
                    acc[r][0] += a * b4.x;
                    acc[r][1] += a * b4.y;
                    acc[r][2] += a * b4.z;
                    acc[r][3] += a * b4.w;
                }
            }
        }

        // epilogue for this n-chunk: tanh + v-weighted sum
        const int nc = n0 + tx * 4;
        #pragma unroll
        for (int r = 0; r < 4; r++) {
            #pragma unroll
            for (int c = 0; c < 4; c++) {
                float x = acc[r][c] + hWp[r][nc + c];
                rowsum[r] += sv[nc + c] * tanhf(x);
            }
        }
    }

    // reduce rowsum across the 16 tx lanes (lanes 0..15 within half-warp)
    #pragma unroll
    for (int r = 0; r < 4; r++) {
        float s = rowsum[r];
        s += __shfl_down_sync(0xffffffffu, s, 8);
        s += __shfl_down_sync(0xffffffffu, s, 4);
        s += __shfl_down_sync(0xffffffffu, s, 2);
        s += __shfl_down_sync(0xffffffffu, s, 1);
        rowsum[r] = s;
    }
    if (tx == 0) {
        #pragma unroll
        for (int r = 0; r < 4; r++)
            g_logits[m0 + ty * 4 + r] = rowsum[r];
    }
}

// ---------------------------------------------------------------------------
// Kernel 3: row softmax over S=1000 per batch. grid(64), block(256)
// ---------------------------------------------------------------------------
__global__ void softmax_kernel(float* __restrict__ out) {
    __shared__ float red[256];
    const int b = blockIdx.x;
    const int t = threadIdx.x;
    const float* row = g_logits + b * S_;
    float* orow = out + b * S_;

    // max
    float mx = -INFINITY;
    for (int i = t; i < S_; i += 256) mx = fmaxf(mx, row[i]);
    red[t] = mx;
    __syncthreads();
    for (int off = 128; off > 0; off >>= 1) {
        if (t < off) red[t] = fmaxf(red[t], red[t + off]);
        __syncthreads();
    }
    mx = red[0];
    __syncthreads();

    // exp + sum
    float sum = 0.f;
    for (int i = t; i < S_; i += 256) {
        float e = expf(row[i] - mx);
        orow[i] = e;
        sum += e;
    }
    red[t] = sum;
    __syncthreads();
    for (int off = 128; off > 0; off >>= 1) {
        if (t < off) red[t] += red[t + off];
        __syncthreads();
    }
    const float inv = 1.f / red[0];
    __syncthreads();

    for (int i = t; i < S_; i += 256) orow[i] *= inv;
}

// ---------------------------------------------------------------------------
extern "C" void kernel_launch(void* const* d_in, const int* in_sizes, int n_in,
                              void* d_out, int out_size) {
    const float* hidden = (const float*)d_in[0];   // [64, 512]
    const float* enc    = (const float*)d_in[1];   // [64, 1000, 1024]
    const float* attn_w = (const float*)d_in[2];   // [1536, 512]
    const float* attn_b = (const float*)d_in[3];   // [512]
    const float* v      = (const float*)d_in[4];   // [512]
    float* out = (float*)d_out;                    // [64, 1000]

    hw_kernel<<<B_, D_>>>(hidden, attn_w, attn_b);
    attn_gemm_kernel<<<M_ / TM, 256>>>(enc, attn_w, v);
    softmax_kernel<<<B_, 256>>>(out);
}

// round 4
// speedup vs baseline: 2.4127x; 2.4127x over previous
#include <cuda_runtime.h>
#include <cuda_bf16.h>
#include <math.h>
#include <stdint.h>

// ---------------------------------------------------------------- constants
#define B_   64
#define S_   1000
#define D_   512          // N of the GEMM
#define K2_  1024         // K of the GEMM
#define M_   (B_ * S_)    // 64000

#define TMM  128          // CTA M tile
#define KC   64           // K chunk (64 bf16 = 128B swizzled rows)
#define NCH  16           // K2_/KC

// ------------------------------------------------------------- device scratch
__device__ float g_hW[B_ * D_];
__device__ float g_logits[M_];
// W_bot pre-split (hi/lo bf16), pre-transposed to [N,K], pre-swizzled:
// [chunk 16][n 512][128 bytes]  -> 1 MB each
__device__ __align__(16) uint8_t g_wprep_hi[NCH * D_ * 128];
__device__ __align__(16) uint8_t g_wprep_lo[NCH * D_ * 128];

// ---------------------------------------------------------------- smem layout
// A: [stage][hi/lo][128 rows][128B]   -> 2*2*16KB = 64KB
// B: [stage][hi/lo][256 rows][128B]   -> 2*2*32KB = 128KB
#define SA(st, lo)  ((st) * 32768 + (lo) * 16384)
#define SB(st, lo)  (65536 + (st) * 65536 + (lo) * 32768)
#define SM_SV   196608
#define SM_HW0  198656
#define SM_HW1  200704
#define SM_RS   202752
#define SM_TOTAL 203264

// ---------------------------------------------------------------- helpers
__device__ __forceinline__ uint32_t smem_u32(const void* p) {
    uint32_t a;
    asm("{ .reg .u64 t; cvta.to.shared.u64 t, %1; cvt.u32.u64 %0, t; }" : "=r"(a) : "l"(p));
    return a;
}
__host__ __device__ __forceinline__ uint32_t swz128(uint32_t off) {
    return off ^ ((off >> 3) & 0x70);
}
#define LDSM4(R, A)                                                             \
    asm volatile("ldmatrix.sync.aligned.m8n8.x4.shared.b16 {%0,%1,%2,%3}, [%4];" \
        : "=r"((R)[0]), "=r"((R)[1]), "=r"((R)[2]), "=r"((R)[3]) : "r"(A))
__device__ __forceinline__ void mma_bf16(float* c, const uint32_t* a, const uint32_t* b) {
    asm volatile("mma.sync.aligned.m16n8k16.row.col.f32.bf16.bf16.f32 "
        "{%0,%1,%2,%3},{%4,%5,%6,%7},{%8,%9},{%0,%1,%2,%3};"
        : "+f"(c[0]), "+f"(c[1]), "+f"(c[2]), "+f"(c[3])
        : "r"(a[0]), "r"(a[1]), "r"(a[2]), "r"(a[3]), "r"(b[0]), "r"(b[1]));
}
#define CP16(dst, src) \
    asm volatile("cp.async.cg.shared.global [%0], [%1], 16;" :: "r"(dst), "l"(src) : "memory")
#define CP_COMMIT() asm volatile("cp.async.commit_group;" ::: "memory")
#define CP_WAIT0()  asm volatile("cp.async.wait_group 0;" ::: "memory")

// ---------------------------------------------------------------------------
// hW[b][n] = attn_b[n] + hidden[b] @ W_top[:,n]    grid(64,4) x 128
// ---------------------------------------------------------------------------
__global__ void hw_kernel(const float* __restrict__ hidden,
                          const float* __restrict__ attn_w,
                          const float* __restrict__ attn_b) {
    __shared__ float sh[D_];
    const int b = blockIdx.x;
    const int n = blockIdx.y * 128 + threadIdx.x;
    for (int i = threadIdx.x; i < D_; i += 128) sh[i] = hidden[b * D_ + i];
    __syncthreads();
    float a0 = 0.f, a1 = 0.f, a2 = 0.f, a3 = 0.f;
    #pragma unroll 4
    for (int k = 0; k < D_; k += 4) {
        a0 += sh[k + 0] * attn_w[(k + 0) * D_ + n];
        a1 += sh[k + 1] * attn_w[(k + 1) * D_ + n];
        a2 += sh[k + 2] * attn_w[(k + 2) * D_ + n];
        a3 += sh[k + 3] * attn_w[(k + 3) * D_ + n];
    }
    g_hW[b * D_ + n] = attn_b[n] + ((a0 + a1) + (a2 + a3));
}

// ---------------------------------------------------------------------------
// Split W_bot into bf16 hi/lo, transposed [n][k] + SW128-swizzled tile images.
// grid(16 chunks, 4 k-groups), block(512 = n)
// ---------------------------------------------------------------------------
__global__ void conv_w_kernel(const float* __restrict__ attn_w) {
    const int chunk = blockIdx.x;
    const int n = threadIdx.x;
    uint8_t* dh = g_wprep_hi + chunk * (D_ * 128);
    uint8_t* dl = g_wprep_lo + chunk * (D_ * 128);
    for (int kk = blockIdx.y * 16; kk < blockIdx.y * 16 + 16; kk++) {
        const int kg = D_ + chunk * KC + kk;
        float w = attn_w[(size_t)kg * D_ + n];
        __nv_bfloat16 hi = __float2bfloat16(w);
        __nv_bfloat16 lo = __float2bfloat16(w - __bfloat162float(hi));
        uint32_t sw = swz128((uint32_t)(n * 128 + kk * 2));
        *reinterpret_cast<uint16_t*>(dh + sw) = *reinterpret_cast<uint16_t*>(&hi);
        *reinterpret_cast<uint16_t*>(dl + sw) = *reinterpret_cast<uint16_t*>(&lo);
    }
}

// ---------------------------------------------------------------------------
// Main HMMA GEMM + tanh + v-dot.  grid(500), block(512) = 16 warps (4M x 4N)
// ---------------------------------------------------------------------------
__global__ __launch_bounds__(512, 1)
void gemm_kernel(const float* __restrict__ enc, const float* __restrict__ v) {
    extern __shared__ __align__(1024) uint8_t smem[];
    const uint32_t sb = smem_u32(smem);
    const int tid  = threadIdx.x;
    const int wid  = tid >> 5;
    const int lane = tid & 31;
    const int wm   = wid >> 2;          // 0..3  (M quadrant, 32 rows)
    const int wn   = wid & 3;           // 0..3  (N quadrant, 64 cols)
    const int m0   = blockIdx.x * TMM;

    float* svp = reinterpret_cast<float*>(smem + SM_SV);
    float* hw0 = reinterpret_cast<float*>(smem + SM_HW0);
    float* hw1 = reinterpret_cast<float*>(smem + SM_HW1);
    float* rsm = reinterpret_cast<float*>(smem + SM_RS);

    const int b0 = m0 / S_;
    const int b1 = (m0 + TMM - 1) / S_;
    const int thr = (b0 + 1) * S_ - m0;   // rows >= thr belong to b1
    for (int i = tid; i < D_; i += 512) {
        svp[i] = v[i];
        hw0[i] = g_hW[b0 * D_ + i];
        hw1[i] = g_hW[b1 * D_ + i];
    }
    if (tid < TMM) rsm[tid] = 0.f;

    // ---- per-lane ldmatrix address components ------------------------------
    // A frag (16x16): matrices 0,1 = rows 0-7/8-15 @k; 2,3 = same rows @k+16B
    const int a_r16  = lane & 15;
    const uint32_t a_kext = (lane >> 4) << 4;
    uint32_t aoff[2], asw[2];
    #pragma unroll
    for (int ms = 0; ms < 2; ms++) {
        int r = wm * 32 + ms * 16 + a_r16;
        aoff[ms] = (uint32_t)r * 128;
        asw[ms]  = (uint32_t)(r & 7) << 4;
    }
    // B frag pairs (16n x 16k): matrices 0,1 = rows n..n+7 @k,@k+16B; 2,3 = rows+8
    const int b_r16  = (lane & 7) | ((lane & 16) >> 1);
    const uint32_t b_kext = (lane & 8) << 1;
    uint32_t boff[4], bsw[4];
    #pragma unroll
    for (int np = 0; np < 4; np++) {
        int r = wn * 64 + np * 16 + b_r16;
        boff[np] = (uint32_t)r * 128;
        bsw[np]  = (uint32_t)(r & 7) << 4;
    }

    // ---- A loader: LDG float4, split to bf16 hi/lo, STS swizzled -----------
    const int arow = tid >> 2;          // 0..127
    const int akg  = tid & 3;           // 16-float group
    const size_t abase = (size_t)(m0 + arow) * K2_;
    const uint32_t a_sw = (uint32_t)(arow & 7) << 4;
    const uint32_t a_ro = (uint32_t)arow * 128;

    auto ldgA = [&](int chunk, float4* h) {
        const float4* p = reinterpret_cast<const float4*>(enc + abase + chunk * KC + akg * 16);
        #pragma unroll
        for (int j = 0; j < 4; j++) h[j] = p[j];
    };
    auto stA = [&](const float4* h, int st) {
        #pragma unroll
        for (int j = 0; j < 4; j++) {
            float4 f = h[j];
            __nv_bfloat16 h0 = __float2bfloat16(f.x);
            __nv_bfloat16 h1 = __float2bfloat16(f.y);
            __nv_bfloat16 h2 = __float2bfloat16(f.z);
            __nv_bfloat16 h3 = __float2bfloat16(f.w);
            __nv_bfloat16 l0 = __float2bfloat16(f.x - __bfloat162float(h0));
            __nv_bfloat16 l1 = __float2bfloat16(f.y - __bfloat162float(h1));
            __nv_bfloat16 l2 = __float2bfloat16(f.z - __bfloat162float(h2));
            __nv_bfloat16 l3 = __float2bfloat16(f.w - __bfloat162float(h3));
            __nv_bfloat162 hp0 = __halves2bfloat162(h0, h1);
            __nv_bfloat162 hp1 = __halves2bfloat162(h2, h3);
            __nv_bfloat162 lp0 = __halves2bfloat162(l0, l1);
            __nv_bfloat162 lp1 = __halves2bfloat162(l2, l3);
            uint2 uh = make_uint2(*reinterpret_cast<uint32_t*>(&hp0),
                                  *reinterpret_cast<uint32_t*>(&hp1));
            uint2 ul = make_uint2(*reinterpret_cast<uint32_t*>(&lp0),
                                  *reinterpret_cast<uint32_t*>(&lp1));
            uint32_t off = a_ro + (((uint32_t)(akg * 32 + j * 8)) ^ a_sw);
            *reinterpret_cast<uint2*>(smem + SA(st, 0) + off) = uh;
            *reinterpret_cast<uint2*>(smem + SA(st, 1) + off) = ul;
        }
    };
    // ---- B loader: cp.async 16B copies of pre-swizzled images --------------
    auto loadB = [&](int pass, int chunk, int st) {
        const uint8_t* gh = g_wprep_hi + chunk * (D_ * 128) + pass * (256 * 128);
        const uint8_t* gl = g_wprep_lo + chunk * (D_ * 128) + pass * (256 * 128);
        const uint32_t dh = sb + SB(st, 0);
        const uint32_t dl = sb + SB(st, 1);
        #pragma unroll
        for (int j = 0; j < 4; j++) {
            uint32_t idx = (uint32_t)(tid + j * 512) * 16;
            CP16(dh + idx, gh + idx);
            CP16(dl + idx, gl + idx);
        }
        CP_COMMIT();
    };

    float acc[2][8][4];

    // ---- compute one 64-K chunk from stage st ------------------------------
    auto compute = [&](int st) {
        const uint32_t baseAh = sb + SA(st, 0);
        const uint32_t baseAl = sb + SA(st, 1);
        const uint32_t baseBh = sb + SB(st, 0);
        const uint32_t baseBl = sb + SB(st, 1);
        #pragma unroll
        for (int k16 = 0; k16 < 4; k16++) {
            const uint32_t ka = (uint32_t)(k16 * 32) + a_kext;
            const uint32_t kb = (uint32_t)(k16 * 32) + b_kext;
            uint32_t ah[2][4], al[2][4];
            #pragma unroll
            for (int ms = 0; ms < 2; ms++) {
                uint32_t o = aoff[ms] + (ka ^ asw[ms]);
                LDSM4(ah[ms], baseAh + o);
                LDSM4(al[ms], baseAl + o);
            }
            #pragma unroll
            for (int np = 0; np < 4; np++) {
                const uint32_t o = boff[np] + (kb ^ bsw[np]);
                uint32_t bh[4], bl[4];
                LDSM4(bh, baseBh + o);
                #pragma unroll
                for (int ms = 0; ms < 2; ms++) {
                    mma_bf16(acc[ms][np * 2 + 0], ah[ms], bh + 0);
                    mma_bf16(acc[ms][np * 2 + 1], ah[ms], bh + 2);
                    mma_bf16(acc[ms][np * 2 + 0], al[ms], bh + 0);
                    mma_bf16(acc[ms][np * 2 + 1], al[ms], bh + 2);
                }
                LDSM4(bl, baseBl + o);
                #pragma unroll
                for (int ms = 0; ms < 2; ms++) {
                    mma_bf16(acc[ms][np * 2 + 0], ah[ms], bl + 0);
                    mma_bf16(acc[ms][np * 2 + 1], ah[ms], bl + 2);
                }
            }
        }
    };

    const int gid = lane >> 2;
    const int tig = lane & 3;

    // ======================= two N-passes ====================================
    #pragma unroll 1
    for (int pass = 0; pass < 2; pass++) {
        #pragma unroll
        for (int ms = 0; ms < 2; ms++)
            #pragma unroll
            for (int ns = 0; ns < 8; ns++)
                #pragma unroll
                for (int c = 0; c < 4; c++) acc[ms][ns][c] = 0.f;

        // prologue: chunk 0 -> stage 0
        loadB(pass, 0, 0);
        { float4 h[4]; ldgA(0, h); stA(h, 0); }
        CP_WAIT0();
        __syncthreads();

        #pragma unroll 1
        for (int i = 0; i < NCH; i++) {
            const int s = i & 1;
            float4 h[4];
            const bool pf = (i + 1 < NCH);
            if (pf) { loadB(pass, i + 1, s ^ 1); ldgA(i + 1, h); }
            compute(s);
            if (pf) stA(h, s ^ 1);
            CP_WAIT0();
            __syncthreads();
        }

        // epilogue: x = acc + hW, rowsum += v * tanh(x)
        #pragma unroll
        for (int ms = 0; ms < 2; ms++) {
            #pragma unroll
            for (int ch = 0; ch < 2; ch++) {
                const int r = wm * 32 + ms * 16 + ch * 8 + gid;
                const float* hwrow = (r >= thr) ? hw1 : hw0;
                float rs = 0.f;
                #pragma unroll
                for (int ns = 0; ns < 8; ns++) {
                    const int n = pass * 256 + wn * 64 + ns * 8 + tig * 2;
                    float x0 = acc[ms][ns][ch * 2 + 0] + hwrow[n];
                    float x1 = acc[ms][ns][ch * 2 + 1] + hwrow[n + 1];
                    rs += svp[n] * tanhf(x0) + svp[n + 1] * tanhf(x1);
                }
                rs += __shfl_xor_sync(0xffffffffu, rs, 1);
                rs += __shfl_xor_sync(0xffffffffu, rs, 2);
                if (tig == 0) atomicAdd(&rsm[r], rs);
            }
        }
    }

    __syncthreads();
    if (tid < TMM) g_logits[m0 + tid] = rsm[tid];
}

// ---------------------------------------------------------------------------
// softmax over S per batch. grid(64), block(256)
// ---------------------------------------------------------------------------
__global__ void softmax_kernel(float* __restrict__ out) {
    __shared__ float red[256];
    const int b = blockIdx.x;
    const int t = threadIdx.x;
    const float* row = g_logits + b * S_;
    float* orow = out + b * S_;

    float mx = -INFINITY;
    for (int i = t; i < S_; i += 256) mx = fmaxf(mx, row[i]);
    red[t] = mx;
    __syncthreads();
    for (int off = 128; off > 0; off >>= 1) {
        if (t < off) red[t] = fmaxf(red[t], red[t + off]);
        __syncthreads();
    }
    mx = red[0];
    __syncthreads();

    float sum = 0.f;
    for (int i = t; i < S_; i += 256) {
        float e = expf(row[i] - mx);
        orow[i] = e;
        sum += e;
    }
    red[t] = sum;
    __syncthreads();
    for (int off = 128; off > 0; off >>= 1) {
        if (t < off) red[t] += red[t + off];
        __syncthreads();
    }
    const float inv = 1.f / red[0];
    __syncthreads();
    for (int i = t; i < S_; i += 256) orow[i] *= inv;
}

// ---------------------------------------------------------------------------
extern "C" void kernel_launch(void* const* d_in, const int* in_sizes, int n_in,
                              void* d_out, int out_size) {
    const float* hidden = (const float*)d_in[0];   // [64, 512]
    const float* enc    = (const float*)d_in[1];   // [64, 1000, 1024]
    const float* attn_w = (const float*)d_in[2];   // [1536, 512]
    const float* attn_b = (const float*)d_in[3];   // [512]
    const float* v      = (const float*)d_in[4];   // [512]
    float* out = (float*)d_out;                    // [64, 1000]

    cudaFuncSetAttribute(gemm_kernel,
                         cudaFuncAttributeMaxDynamicSharedMemorySize, SM_TOTAL);

    conv_w_kernel<<<dim3(NCH, 4), D_>>>(attn_w);
    hw_kernel<<<dim3(B_, 4), 128>>>(hidden, attn_w, attn_b);
    gemm_kernel<<<M_ / TMM, 512, SM_TOTAL>>>(enc, v);
    softmax_kernel<<<B_, 256>>>(out);
}

// round 5
// speedup vs baseline: 2.4584x; 1.0189x over previous
#include <cuda_runtime.h>
#include <cuda_bf16.h>
#include <math.h>
#include <stdint.h>

// ---------------------------------------------------------------- constants
#define B_   64
#define S_   1000
#define D_   512          // N of the GEMM
#define K2_  1024         // K of the GEMM
#define M_   (B_ * S_)    // 64000

#define TMM  128          // CTA M tile
#define KC   64           // K chunk (64 bf16 = 128B swizzled rows)
#define NCH  16           // K2_/KC

// ------------------------------------------------------------- device scratch
__device__ float g_hW[B_ * D_];
__device__ float g_logits[M_];
// W_bot pre-split (hi/lo bf16), transposed [n][k], SW128-swizzled per chunk
__device__ __align__(16) uint8_t g_wprep_hi[NCH * D_ * 128];
__device__ __align__(16) uint8_t g_wprep_lo[NCH * D_ * 128];
// enc pre-split to bf16 hi/lo, row-major [M_][K2_] (2KB rows)
__device__ __align__(16) uint8_t g_enc_hi[(size_t)M_ * K2_ * 2];
__device__ __align__(16) uint8_t g_enc_lo[(size_t)M_ * K2_ * 2];

// ---------------------------------------------------------------- smem layout
// A: [stage][hi/lo][128 rows][128B]   -> 2*2*16KB = 64KB
// B: [stage][hi/lo][256 rows][128B]   -> 2*2*32KB = 128KB
#define SA(st, lo)  ((st) * 32768 + (lo) * 16384)
#define SB(st, lo)  (65536 + (st) * 65536 + (lo) * 32768)
#define SM_SV   196608
#define SM_HW0  198656
#define SM_HW1  200704
#define SM_RS   202752
#define SM_TOTAL 203264

// ---------------------------------------------------------------- helpers
__device__ __forceinline__ uint32_t smem_u32(const void* p) {
    uint32_t a;
    asm("{ .reg .u64 t; cvta.to.shared.u64 t, %1; cvt.u32.u64 %0, t; }" : "=r"(a) : "l"(p));
    return a;
}
__host__ __device__ __forceinline__ uint32_t swz128(uint32_t off) {
    return off ^ ((off >> 3) & 0x70);
}
#define LDSM4(R, A)                                                             \
    asm volatile("ldmatrix.sync.aligned.m8n8.x4.shared.b16 {%0,%1,%2,%3}, [%4];" \
        : "=r"((R)[0]), "=r"((R)[1]), "=r"((R)[2]), "=r"((R)[3]) : "r"(A))
__device__ __forceinline__ void mma_bf16(float* c, const uint32_t* a, const uint32_t* b) {
    asm volatile("mma.sync.aligned.m16n8k16.row.col.f32.bf16.bf16.f32 "
        "{%0,%1,%2,%3},{%4,%5,%6,%7},{%8,%9},{%0,%1,%2,%3};"
        : "+f"(c[0]), "+f"(c[1]), "+f"(c[2]), "+f"(c[3])
        : "r"(a[0]), "r"(a[1]), "r"(a[2]), "r"(a[3]), "r"(b[0]), "r"(b[1]));
}
#define CP16(dst, src) \
    asm volatile("cp.async.cg.shared.global [%0], [%1], 16;" :: "r"(dst), "l"(src) : "memory")
#define CP_COMMIT() asm volatile("cp.async.commit_group;" ::: "memory")
#define CP_WAIT0()  asm volatile("cp.async.wait_group 0;" ::: "memory")
#define CP_WAIT1()  asm volatile("cp.async.wait_group 1;" ::: "memory")

// ---------------------------------------------------------------------------
// hW[b][n] = attn_b[n] + hidden[b] @ W_top[:,n]    grid(64,4) x 128
// ---------------------------------------------------------------------------
__global__ void hw_kernel(const float* __restrict__ hidden,
                          const float* __restrict__ attn_w,
                          const float* __restrict__ attn_b) {
    __shared__ float sh[D_];
    const int b = blockIdx.x;
    const int n = blockIdx.y * 128 + threadIdx.x;
    for (int i = threadIdx.x; i < D_; i += 128) sh[i] = hidden[b * D_ + i];
    __syncthreads();
    float a0 = 0.f, a1 = 0.f, a2 = 0.f, a3 = 0.f;
    #pragma unroll 4
    for (int k = 0; k < D_; k += 4) {
        a0 += sh[k + 0] * attn_w[(k + 0) * D_ + n];
        a1 += sh[k + 1] * attn_w[(k + 1) * D_ + n];
        a2 += sh[k + 2] * attn_w[(k + 2) * D_ + n];
        a3 += sh[k + 3] * attn_w[(k + 3) * D_ + n];
    }
    g_hW[b * D_ + n] = attn_b[n] + ((a0 + a1) + (a2 + a3));
}

// ---------------------------------------------------------------------------
// Split W_bot into bf16 hi/lo, transposed [n][k] + SW128-swizzled tile images.
// grid(16 chunks, 4 k-groups), block(512 = n)
// ---------------------------------------------------------------------------
__global__ void conv_w_kernel(const float* __restrict__ attn_w) {
    const int chunk = blockIdx.x;
    const int n = threadIdx.x;
    uint8_t* dh = g_wprep_hi + chunk * (D_ * 128);
    uint8_t* dl = g_wprep_lo + chunk * (D_ * 128);
    for (int kk = blockIdx.y * 16; kk < blockIdx.y * 16 + 16; kk++) {
        const int kg = D_ + chunk * KC + kk;
        float w = attn_w[(size_t)kg * D_ + n];
        __nv_bfloat16 hi = __float2bfloat16(w);
        __nv_bfloat16 lo = __float2bfloat16(w - __bfloat162float(hi));
        uint32_t sw = swz128((uint32_t)(n * 128 + kk * 2));
        *reinterpret_cast<uint16_t*>(dh + sw) = *reinterpret_cast<uint16_t*>(&hi);
        *reinterpret_cast<uint16_t*>(dl + sw) = *reinterpret_cast<uint16_t*>(&lo);
    }
}

// ---------------------------------------------------------------------------
// Split enc into bf16 hi/lo, plain row-major. grid(16000), block(256): 4 rows/CTA
// ---------------------------------------------------------------------------
__global__ __launch_bounds__(256)
void conv_enc_kernel(const float* __restrict__ enc) {
    const int r = blockIdx.x * 4 + (threadIdx.x >> 6);
    const int c = (threadIdx.x & 63) * 16;
    const float4* p = reinterpret_cast<const float4*>(enc + (size_t)r * K2_ + c);
    uint2* dh = reinterpret_cast<uint2*>(g_enc_hi + (size_t)r * (K2_ * 2) + c * 2);
    uint2* dl = reinterpret_cast<uint2*>(g_enc_lo + (size_t)r * (K2_ * 2) + c * 2);
    #pragma unroll
    for (int j = 0; j < 4; j++) {
        float4 f = p[j];
        __nv_bfloat16 h0 = __float2bfloat16(f.x);
        __nv_bfloat16 h1 = __float2bfloat16(f.y);
        __nv_bfloat16 h2 = __float2bfloat16(f.z);
        __nv_bfloat16 h3 = __float2bfloat16(f.w);
        __nv_bfloat16 l0 = __float2bfloat16(f.x - __bfloat162float(h0));
        __nv_bfloat16 l1 = __float2bfloat16(f.y - __bfloat162float(h1));
        __nv_bfloat16 l2 = __float2bfloat16(f.z - __bfloat162float(h2));
        __nv_bfloat16 l3 = __float2bfloat16(f.w - __bfloat162float(h3));
        __nv_bfloat162 hp0 = __halves2bfloat162(h0, h1);
        __nv_bfloat162 hp1 = __halves2bfloat162(h2, h3);
        __nv_bfloat162 lp0 = __halves2bfloat162(l0, l1);
        __nv_bfloat162 lp1 = __halves2bfloat162(l2, l3);
        dh[j] = make_uint2(*reinterpret_cast<uint32_t*>(&hp0),
                           *reinterpret_cast<uint32_t*>(&hp1));
        dl[j] = make_uint2(*reinterpret_cast<uint32_t*>(&lp0),
                           *reinterpret_cast<uint32_t*>(&lp1));
    }
}

// no-op pad launches (position gemm_kernel as the 6th launch for ncu -s 5)
__global__ void noop_kernel() {}

// ---------------------------------------------------------------------------
// Main HMMA GEMM + tanh + v-dot.  grid(500), block(512) = 16 warps (4M x 4N)
// Pure cp.async -> ldmatrix -> mma pipeline; A pre-converted in gmem.
// ---------------------------------------------------------------------------
__global__ __launch_bounds__(512, 1)
void gemm_kernel(const float* __restrict__ v) {
    extern __shared__ __align__(1024) uint8_t smem[];
    const uint32_t sb = smem_u32(smem);
    const int tid  = threadIdx.x;
    const int wid  = tid >> 5;
    const int lane = tid & 31;
    const int wm   = wid >> 2;          // 0..3 (M quadrant, 32 rows)
    const int wn   = wid & 3;           // 0..3 (N quadrant, 64 cols)
    const int m0   = blockIdx.x * TMM;

    float* svp = reinterpret_cast<float*>(smem + SM_SV);
    float* hw0 = reinterpret_cast<float*>(smem + SM_HW0);
    float* hw1 = reinterpret_cast<float*>(smem + SM_HW1);
    float* rsm = reinterpret_cast<float*>(smem + SM_RS);

    const int b0 = m0 / S_;
    const int b1 = (m0 + TMM - 1) / S_;
    const int thr = (b0 + 1) * S_ - m0;   // rows >= thr belong to b1
    for (int i = tid; i < D_; i += 512) {
        svp[i] = v[i];
        hw0[i] = g_hW[b0 * D_ + i];
        hw1[i] = g_hW[b1 * D_ + i];
    }
    if (tid < TMM) rsm[tid] = 0.f;

    // ---- per-lane ldmatrix address components ------------------------------
    const int a_r16  = lane & 15;
    const uint32_t a_kext = (lane >> 4) << 4;
    uint32_t aoff[2], asw[2];
    #pragma unroll
    for (int ms = 0; ms < 2; ms++) {
        int r = wm * 32 + ms * 16 + a_r16;
        aoff[ms] = (uint32_t)r * 128;
        asw[ms]  = (uint32_t)(r & 7) << 4;
    }
    const int b_r16  = (lane & 7) | ((lane & 16) >> 1);
    const uint32_t b_kext = (lane & 8) << 1;
    uint32_t boff[4], bsw[4];
    #pragma unroll
    for (int np = 0; np < 4; np++) {
        int r = wn * 64 + np * 16 + b_r16;
        boff[np] = (uint32_t)r * 128;
        bsw[np]  = (uint32_t)(r & 7) << 4;
    }

    // ---- cp.async loader: A (hi/lo, 1024 pieces each) + B (pre-swizzled) ----
    // A piece p (0..1023): row=p>>3, c16=p&7; dst swizzled within 128B rows.
    const uint32_t ap0 = (uint32_t)tid;          // j=0 piece
    const uint32_t ap1 = (uint32_t)tid + 512;    // j=1 piece
    auto loadAB = [&](int pass, int chunk, int st) {
        #pragma unroll
        for (int j = 0; j < 2; j++) {
            uint32_t p = j ? ap1 : ap0;
            uint32_t row = p >> 3, c16 = p & 7;
            uint32_t dsto = row * 128 + ((c16 << 4) ^ ((row & 7) << 4));
            size_t   srco = (size_t)(m0 + row) * (K2_ * 2) + chunk * 128 + (c16 << 4);
            CP16(sb + SA(st, 0) + dsto, g_enc_hi + srco);
            CP16(sb + SA(st, 1) + dsto, g_enc_lo + srco);
        }
        const uint8_t* gh = g_wprep_hi + chunk * (D_ * 128) + pass * (256 * 128);
        const uint8_t* gl = g_wprep_lo + chunk * (D_ * 128) + pass * (256 * 128);
        #pragma unroll
        for (int j = 0; j < 4; j++) {
            uint32_t idx = (uint32_t)(tid + j * 512) * 16;
            CP16(sb + SB(st, 0) + idx, gh + idx);
            CP16(sb + SB(st, 1) + idx, gl + idx);
        }
        CP_COMMIT();
    };

    float acc[2][8][4];

    auto compute = [&](int st) {
        const uint32_t baseAh = sb + SA(st, 0);
        const uint32_t baseAl = sb + SA(st, 1);
        const uint32_t baseBh = sb + SB(st, 0);
        const uint32_t baseBl = sb + SB(st, 1);
        #pragma unroll
        for (int k16 = 0; k16 < 4; k16++) {
            const uint32_t ka = (uint32_t)(k16 * 32) + a_kext;
            const uint32_t kb = (uint32_t)(k16 * 32) + b_kext;
            uint32_t ah[2][4], al[2][4];
            #pragma unroll
            for (int ms = 0; ms < 2; ms++) {
                uint32_t o = aoff[ms] + (ka ^ asw[ms]);
                LDSM4(ah[ms], baseAh + o);
                LDSM4(al[ms], baseAl + o);
            }
            #pragma unroll
            for (int np = 0; np < 4; np++) {
                const uint32_t o = boff[np] + (kb ^ bsw[np]);
                uint32_t bh[4], bl[4];
                LDSM4(bh, baseBh + o);
                #pragma unroll
                for (int ms = 0; ms < 2; ms++) {
                    mma_bf16(acc[ms][np * 2 + 0], ah[ms], bh + 0);
                    mma_bf16(acc[ms][np * 2 + 1], ah[ms], bh + 2);
                    mma_bf16(acc[ms][np * 2 + 0], al[ms], bh + 0);
                    mma_bf16(acc[ms][np * 2 + 1], al[ms], bh + 2);
                }
                LDSM4(bl, baseBl + o);
                #pragma unroll
                for (int ms = 0; ms < 2; ms++) {
                    mma_bf16(acc[ms][np * 2 + 0], ah[ms], bl + 0);
                    mma_bf16(acc[ms][np * 2 + 1], ah[ms], bl + 2);
                }
            }
        }
    };

    const int gid = lane >> 2;
    const int tig = lane & 3;

    // ======================= two N-passes ====================================
    #pragma unroll 1
    for (int pass = 0; pass < 2; pass++) {
        #pragma unroll
        for (int ms = 0; ms < 2; ms++)
            #pragma unroll
            for (int ns = 0; ns < 8; ns++)
                #pragma unroll
                for (int c = 0; c < 4; c++) acc[ms][ns][c] = 0.f;

        loadAB(pass, 0, 0);

        #pragma unroll 1
        for (int i = 0; i < NCH; i++) {
            const int s = i & 1;
            const bool pf = (i + 1 < NCH);
            if (pf) { loadAB(pass, i + 1, s ^ 1); CP_WAIT1(); }
            else    { CP_WAIT0(); }
            __syncthreads();           // stage s visible to all
            compute(s);
            __syncthreads();           // all readers of stage s done
        }

        // epilogue: x = acc + hW, rowsum += v * tanh(x)
        #pragma unroll
        for (int ms = 0; ms < 2; ms++) {
            #pragma unroll
            for (int ch = 0; ch < 2; ch++) {
                const int r = wm * 32 + ms * 16 + ch * 8 + gid;
                const float* hwrow = (r >= thr) ? hw1 : hw0;
                float rs = 0.f;
                #pragma unroll
                for (int ns = 0; ns < 8; ns++) {
                    const int n = pass * 256 + wn * 64 + ns * 8 + tig * 2;
                    float x0 = acc[ms][ns][ch * 2 + 0] + hwrow[n];
                    float x1 = acc[ms][ns][ch * 2 + 1] + hwrow[n + 1];
                    rs += svp[n] * tanhf(x0) + svp[n + 1] * tanhf(x1);
                }
                rs += __shfl_xor_sync(0xffffffffu, rs, 1);
                rs += __shfl_xor_sync(0xffffffffu, rs, 2);
                if (tig == 0) atomicAdd(&rsm[r], rs);
            }
        }
    }

    __syncthreads();
    if (tid < TMM) g_logits[m0 + tid] = rsm[tid];
}

// ---------------------------------------------------------------------------
// softmax over S per batch. grid(64), block(256)
// ---------------------------------------------------------------------------
__global__ void softmax_kernel(float* __restrict__ out) {
    __shared__ float red[256];
    const int b = blockIdx.x;
    const int t = threadIdx.x;
    const float* row = g_logits + b * S_;
    float* orow = out + b * S_;

    float mx = -INFINITY;
    for (int i = t; i < S_; i += 256) mx = fmaxf(mx, row[i]);
    red[t] = mx;
    __syncthreads();
    for (int off = 128; off > 0; off >>= 1) {
        if (t < off) red[t] = fmaxf(red[t], red[t + off]);
        __syncthreads();
    }
    mx = red[0];
    __syncthreads();

    float sum = 0.f;
    for (int i = t; i < S_; i += 256) {
        float e = expf(row[i] - mx);
        orow[i] = e;
        sum += e;
    }
    red[t] = sum;
    __syncthreads();
    for (int off = 128; off > 0; off >>= 1) {
        if (t < off) red[t] += red[t + off];
        __syncthreads();
    }
    const float inv = 1.f / red[0];
    __syncthreads();
    for (int i = t; i < S_; i += 256) orow[i] *= inv;
}

// ---------------------------------------------------------------------------
extern "C" void kernel_launch(void* const* d_in, const int* in_sizes, int n_in,
                              void* d_out, int out_size) {
    const float* hidden = (const float*)d_in[0];   // [64, 512]
    const float* enc    = (const float*)d_in[1];   // [64, 1000, 1024]
    const float* attn_w = (const float*)d_in[2];   // [1536, 512]
    const float* attn_b = (const float*)d_in[3];   // [512]
    const float* v      = (const float*)d_in[4];   // [512]
    float* out = (float*)d_out;                    // [64, 1000]

    cudaFuncSetAttribute(gemm_kernel,
                         cudaFuncAttributeMaxDynamicSharedMemorySize, SM_TOTAL);

    conv_w_kernel<<<dim3(NCH, 4), D_>>>(attn_w);          // L1
    hw_kernel<<<dim3(B_, 4), 128>>>(hidden, attn_w, attn_b); // L2
    conv_enc_kernel<<<M_ / 4, 256>>>(enc);                 // L3
    noop_kernel<<<1, 32>>>();                              // L4 (pad: gemm -> L6)
    noop_kernel<<<1, 32>>>();                              // L5 (pad)
    gemm_kernel<<<M_ / TMM, 512, SM_TOTAL>>>(v);           // L6 <- ncu -s 5 -c 1
    softmax_kernel<<<B_, 256>>>(out);                      // L7
}